// round 14
// baseline (speedup 1.0000x reference)
#include <cuda_runtime.h>
#include <cstdint>

#define BATCH 256
#define SEQ   512
#define DIM   512
#define HID   1024
#define NA    6
#define NS    4

typedef unsigned long long ull;

// ---------------------------------------------------------------------------
// Device scratch (static; no cudaMalloc allowed)
// ---------------------------------------------------------------------------
__device__ float    g_z[(size_t)SEQ * BATCH * HID];       // z [S][B][H]
__device__ __align__(16) unsigned g_bits[3][BATCH][HID / 32]; // spike bitmasks
__device__ unsigned g_barCount;                            // zero-init at load
__device__ unsigned g_barGen;                              // monotonic

#define GRID_SCAN 128

// smem layout (32-bit word offsets)
#define SM_SBITS   0        // 512 words
#define SM_SCOUNT  512      // 16
#define SM_ROWCTR  528      // 1 (+15 pad)
#define SM_SLIST   544      // 16*1024
#define SM_XS      16928    // 8192 floats (x stage: 16 rows x 512)
#define SM_MEM     25120    // 2048 floats (mem: 16 rows x 128 cols)
#define SM_WORDS   27168
#define SMEM_SCAN  (SM_WORDS * 4)

// ---------------------------------------------------------------------------
// Grid barrier (128 blocks, 1/SM -> co-resident; self-restoring across replays)
// ---------------------------------------------------------------------------
__device__ __forceinline__ void grid_barrier() {
    __threadfence();
    __syncthreads();
    if (threadIdx.x == 0) {
        unsigned gen = *(volatile unsigned*)&g_barGen;
        unsigned arr = atomicAdd(&g_barCount, 1u);
        if (arr == GRID_SCAN - 1) {
            g_barCount = 0;
            __threadfence();
            *(volatile unsigned*)&g_barGen = gen + 1u;
        } else {
            while (*(volatile unsigned*)&g_barGen == gen) { }
        }
    }
    __syncthreads();
}

// Packed f32x2 add: each half rounds exactly like scalar add.rn.f32
// (== the reference's fma(1.0, v, acc) chain step).
__device__ __forceinline__ ull padd(ull a, ull b) {
    ull r;
    asm("add.rn.f32x2 %0, %1, %2;" : "=l"(r) : "l"(a), "l"(b));
    return r;
}

// spread 16 bits: bit i -> bit 4i of a 64-bit word
__device__ __forceinline__ ull spread4(unsigned h) {
    ull x = h;
    x = (x | (x << 24)) & 0x000000FF000000FFull;
    x = (x | (x << 12)) & 0x000F000F000F000Full;
    x = (x | (x << 6))  & 0x0303030303030303ull;
    x = (x | (x << 3))  & 0x1111111111111111ull;
    return x;
}

// ---------------------------------------------------------------------------
// Encode one timestep s (warps 12-15, 128 threads). z = relu(x@W_enc + b_enc)
// FLAT ascending-k single-accumulator FFMA chain per element; bias-add and
// relu separately rounded. Bitwise identical to the reference. (Frozen.)
// Warp ew owns 32-col band; thread = 4 rows x 4 cols.
// ---------------------------------------------------------------------------
__device__ __forceinline__ void encode_step(
    int s, int r0, int c0, int tid, int w, int lane,
    float* xs, const float* __restrict__ X,
    const float* __restrict__ W, const float* __restrict__ bias)
{
    // stage x[r0..r0+15][s][:] into smem (128 threads, 64 floats each)
    {
        const int e = tid - 384;            // 0..127
        const int row = e >> 3, seg = e & 7;
        const float* xsrc = X + ((size_t)(r0 + row) * SEQ + s) * DIM + seg * 64;
        float* xdst = xs + row * DIM + seg * 64;
#pragma unroll
        for (int q = 0; q < 16; ++q)
            *(float4*)(xdst + q * 4) = *(const float4*)(xsrc + q * 4);
    }
    asm volatile("bar.sync 1, 128;" ::: "memory");

    const int ew = w - 12;                  // 0..3 -> col band
    const int rq = lane >> 3;               // 0..3 -> rows 4rq..4rq+3
    const int cq = lane & 7;                // 0..7 -> 4 cols
    const int ccol = c0 + ew * 32 + 4 * cq;
    const float* Wp = W + ccol;

    float acc[4][4];
#pragma unroll
    for (int i = 0; i < 4; ++i)
#pragma unroll
        for (int j = 0; j < 4; ++j) acc[i][j] = 0.f;

    for (int k4 = 0; k4 < DIM; k4 += 4) {
        float4 xr[4];
#pragma unroll
        for (int i = 0; i < 4; ++i)
            xr[i] = *(const float4*)&xs[(4 * rq + i) * DIM + k4];
#pragma unroll
        for (int kk = 0; kk < 4; ++kk) {
            float4 wv = *(const float4*)(Wp + (size_t)(k4 + kk) * HID);
#pragma unroll
            for (int i = 0; i < 4; ++i) {
                float xv = (&xr[i].x)[kk];
                acc[i][0] = __fmaf_rn(xv, wv.x, acc[i][0]);
                acc[i][1] = __fmaf_rn(xv, wv.y, acc[i][1]);
                acc[i][2] = __fmaf_rn(xv, wv.z, acc[i][2]);
                acc[i][3] = __fmaf_rn(xv, wv.w, acc[i][3]);
            }
        }
    }

    float4 bb = *(const float4*)(bias + ccol);
#pragma unroll
    for (int i = 0; i < 4; ++i) {
        float4 r;
        r.x = fmaxf(__fadd_rn(acc[i][0], bb.x), 0.f);
        r.y = fmaxf(__fadd_rn(acc[i][1], bb.y), 0.f);
        r.z = fmaxf(__fadd_rn(acc[i][2], bb.z), 0.f);
        r.w = fmaxf(__fadd_rn(acc[i][3], bb.w), 0.f);
        *(float4*)(g_z + ((size_t)s * BATCH + r0 + 4 * rq + i) * HID + ccol) = r;
    }
}

// ---------------------------------------------------------------------------
// Fused persistent kernel: 128 blocks x 512 threads.
// Block = 16 batch rows x 128 hid cols.
// Warps 0-11: consume (dynamic row grabbing); warps 12-15: encode z[t+1].
// Bit layout / lists / chains identical to R13 (proven bitwise-correct).
// ---------------------------------------------------------------------------
__global__ void __launch_bounds__(512, 1) fused_kernel(
    const float* __restrict__ X,      const float* __restrict__ W_enc,
    const float* __restrict__ b_enc,
    const float* __restrict__ V,      const float* __restrict__ b_v,
    const float* __restrict__ W_pol,  const float* __restrict__ b_pol,
    const float* __restrict__ W_size, const float* __restrict__ b_size,
    const float* __restrict__ W_val,  const float* __restrict__ b_val,
    float* __restrict__ out)
{
    extern __shared__ unsigned smx[];
    unsigned* sbits   = smx + SM_SBITS;
    unsigned* scount  = smx + SM_SCOUNT;
    unsigned* rowctr  = smx + SM_ROWCTR;
    unsigned* slist   = smx + SM_SLIST;
    float*    xs      = (float*)(smx + SM_XS);
    float*    smem_mem = (float*)(smx + SM_MEM);

    const int tid  = threadIdx.x;
    const int bid  = blockIdx.x;
    const int rg   = bid >> 3;
    const int cg   = bid & 7;
    const int r0   = rg * 16;
    const int c0   = cg * 128;
    const int w    = tid >> 5;
    const int lane = tid & 31;

    const int  ccons = c0 + 4 * lane;                    // consume: 4 cols
    const char* Vb   = (const char*)V + (size_t)ccons * 4;
    const float4 bv4 = *(const float4*)(b_v + ccons);

    // ------------------------- prolog -------------------------
    (&g_bits[0][r0][0])[tid] = 0u;                       // zero bits buf 0 (ours)
    for (int i = tid; i < 16 * 128; i += 512) smem_mem[i] = 0.f;
    if (w >= 12)
        encode_step(0, r0, c0, tid, w, lane, xs, X, W_enc, b_enc);
    grid_barrier();                                      // bits + z[0] visible

    // ------------------------- main loop ----------------------
    for (int t = 0; t < SEQ; ++t) {
        if (w < 12) {
            if (w < 8) {
                // stage spike bits (512 words by 256 threads)
                const unsigned* curbits = &g_bits[t % 3][0][0] + (size_t)r0 * 32;
                sbits[tid]       = __ldcg(curbits + tid);
                sbits[tid + 256] = __ldcg(curbits + tid + 256);
                if (tid == 0) *rowctr = 0u;
                asm volatile("bar.sync 3, 256;" ::: "memory");
                // build per-row ascending firing lists
                {
                    const int brow = tid >> 4;
                    const int g    = tid & 15;
                    const unsigned* wp = sbits + brow * 32 + 4 * (g >> 1);
                    ull M = 0;
#pragma unroll
                    for (int r = 0; r < 4; ++r) {
                        unsigned ww = wp[r];
                        unsigned h = (g & 1) ? (ww >> 16) : (ww & 0xFFFFu);
                        M |= spread4(h) << r;
                    }
                    unsigned cnt = __popcll(M);
                    unsigned inc = cnt;
#pragma unroll
                    for (int d2 = 1; d2 < 16; d2 <<= 1) {
                        unsigned tt = __shfl_up_sync(0xffffffffu, inc, d2, 16);
                        if ((tid & 15) >= d2) inc += tt;
                    }
                    unsigned wpos = brow * 1024 + (inc - cnt);
                    int jb = g * 64;
                    while (M) {
                        int pos = __ffsll(M) - 1;
                        M &= M - 1;
                        slist[wpos++] = (unsigned)((jb + pos) << 12);
                    }
                    if ((tid & 15) == 15) scount[brow] = inc;
                }
            }
            asm volatile("bar.sync 2, 384;" ::: "memory");

            // dynamic row consumption (12 warps, 16 row tasks)
            for (;;) {
                unsigned myrow = 0;
                if (lane == 0) myrow = atomicAdd(rowctr, 1u);
                myrow = __shfl_sync(0xffffffffu, myrow, 0);
                if (myrow >= 16) break;

                float4 zz = *(const float4*)(g_z +
                               ((size_t)t * BATCH + r0 + myrow) * HID + ccons);

                const int n = scount[myrow];
                const unsigned* lp = slist + myrow * 1024;
                ull a0 = 0ull, a1 = 0ull;
                int i = 0;
                for (; i + 8 <= n; i += 8) {
                    uint4 oa = *(const uint4*)(lp + i);
                    uint4 ob = *(const uint4*)(lp + i + 4);
                    ulonglong2 v0 = *(const ulonglong2*)(Vb + oa.x);
                    ulonglong2 v1 = *(const ulonglong2*)(Vb + oa.y);
                    ulonglong2 v2 = *(const ulonglong2*)(Vb + oa.z);
                    ulonglong2 v3 = *(const ulonglong2*)(Vb + oa.w);
                    ulonglong2 v4 = *(const ulonglong2*)(Vb + ob.x);
                    ulonglong2 v5 = *(const ulonglong2*)(Vb + ob.y);
                    ulonglong2 v6 = *(const ulonglong2*)(Vb + ob.z);
                    ulonglong2 v7 = *(const ulonglong2*)(Vb + ob.w);
                    a0 = padd(a0, v0.x); a1 = padd(a1, v0.y);
                    a0 = padd(a0, v1.x); a1 = padd(a1, v1.y);
                    a0 = padd(a0, v2.x); a1 = padd(a1, v2.y);
                    a0 = padd(a0, v3.x); a1 = padd(a1, v3.y);
                    a0 = padd(a0, v4.x); a1 = padd(a1, v4.y);
                    a0 = padd(a0, v5.x); a1 = padd(a1, v5.y);
                    a0 = padd(a0, v6.x); a1 = padd(a1, v6.y);
                    a0 = padd(a0, v7.x); a1 = padd(a1, v7.y);
                }
                for (; i < n; ++i) {
                    ulonglong2 v = *(const ulonglong2*)(Vb + lp[i]);
                    a0 = padd(a0, v.x); a1 = padd(a1, v.y);
                }
                float2 g01 = *(float2*)&a0;
                float2 g23 = *(float2*)&a1;

                // membrane (frozen semantics); reset = (incoming mem > 1)
                float* mp = smem_mem + myrow * 128 + 4 * lane;
                float4 m4 = *(float4*)mp;
                float gg[4] = {g01.x, g01.y, g23.x, g23.y};
                float zv[4] = {zz.x, zz.y, zz.z, zz.w};
                float mv[4] = {m4.x, m4.y, m4.z, m4.w};
                float bb[4] = {bv4.x, bv4.y, bv4.z, bv4.w};
                float m[4];
                unsigned np = 0;
#pragma unroll
                for (int k = 0; k < 4; ++k) {
                    float rst = (mv[k] > 1.0f) ? 1.0f : 0.0f;
                    m[k] = __fsub_rn(__fadd_rn(__fadd_rn(
                               __fmaf_rn(0.95f, mv[k], zv[k]), gg[k]), bb[k]), rst);
                    np |= (m[k] > 1.0f ? 1u : 0u) << k;
                }
                *(float4*)mp = make_float4(m[0], m[1], m[2], m[3]);

                unsigned b0 = __ballot_sync(0xffffffffu, (np >> 0) & 1u);
                unsigned b1 = __ballot_sync(0xffffffffu, (np >> 1) & 1u);
                unsigned b2 = __ballot_sync(0xffffffffu, (np >> 2) & 1u);
                unsigned b3 = __ballot_sync(0xffffffffu, (np >> 3) & 1u);
                if (lane == 0) {
                    unsigned* dstb = &g_bits[(t + 1) % 3][0][0];
                    *(uint4*)(dstb + (r0 + myrow) * 32 + 4 * cg) =
                        make_uint4(b0, b1, b2, b3);
                }
            }
        } else {
            if (t + 1 < SEQ)
                encode_step(t + 1, r0, c0, tid, w, lane, xs, X, W_enc, b_enc);
        }

        grid_barrier();
    }

    // ------------------------- heads --------------------------
    // tail spikes in g_bits[512 % 3 == 2]; layout word = 4*(j>>7)+(j&3),
    // bit = (j>>2)&31. No feedback -> ulp-order harmless; flat chains.
    const unsigned* tail = &g_bits[2][0][0];
    if (tid < 22) {
        int r = bid * 2 + tid / 11;
        int o = tid % 11;
        const float* Wp; int stride; float bo_;
        if (o < 6)       { Wp = W_pol  + o;       stride = NA; bo_ = b_pol[o]; }
        else if (o < 10) { Wp = W_size + (o - 6); stride = NS; bo_ = b_size[o - 6]; }
        else             { Wp = W_val;            stride = 1;  bo_ = b_val[0]; }
        float s = 0.f;
        for (int j = 0; j < HID; ++j) {
            unsigned word = __ldcg(tail + r * 32 + (4 * (j >> 7) + (j & 3)));
            if ((word >> ((j >> 2) & 31)) & 1u)
                s = __fadd_rn(s, Wp[(size_t)j * stride]);
        }
        float val = __fadd_rn(s, bo_);
        if (o < 6)       out[r * NA + o] = val;
        else if (o < 10) out[BATCH * NA + r * NS + (o - 6)] = val;
        else             out[BATCH * NA + BATCH * NS + r] = val;
    }
}

// ---------------------------------------------------------------------------
// kernel_launch: ONE persistent launch (encode fused into the scan).
// ---------------------------------------------------------------------------
extern "C" void kernel_launch(void* const* d_in, const int* in_sizes, int n_in,
                              void* d_out, int out_size) {
    const float* x      = (const float*)d_in[0];
    const float* W_enc  = (const float*)d_in[1];
    const float* b_enc  = (const float*)d_in[2];
    const float* V      = (const float*)d_in[3];
    const float* b_v    = (const float*)d_in[4];
    const float* W_pol  = (const float*)d_in[5];
    const float* b_pol  = (const float*)d_in[6];
    const float* W_size = (const float*)d_in[7];
    const float* b_size = (const float*)d_in[8];
    const float* W_val  = (const float*)d_in[9];
    const float* b_val  = (const float*)d_in[10];
    float* out = (float*)d_out;

    cudaFuncSetAttribute(fused_kernel,
        cudaFuncAttributeMaxDynamicSharedMemorySize, SMEM_SCAN);

    fused_kernel<<<GRID_SCAN, 512, SMEM_SCAN>>>(
        x, W_enc, b_enc, V, b_v, W_pol, b_pol, W_size, b_size,
        W_val, b_val, out);
}

// round 15
// speedup vs baseline: 1.7555x; 1.7555x over previous
#include <cuda_runtime.h>
#include <cstdint>

#define BATCH 256
#define SEQ   512
#define DIM   512
#define HID   1024
#define NA    6
#define NS    4

typedef unsigned long long ull;

// ---------------------------------------------------------------------------
// Device scratch (static; no cudaMalloc allowed)
// ---------------------------------------------------------------------------
__device__ float    g_z[(size_t)SEQ * BATCH * HID];       // z [S][B][H]
__device__ __align__(16) unsigned g_bits[3][BATCH][HID / 32]; // spike bitmasks
__device__ unsigned g_grpCnt[16];                          // per-rowgroup barrier
__device__ unsigned g_grpGen[16];

#define GRID_SCAN 128
#define GROUP_SZ  8            // blocks per row-group barrier

// smem layout (32-bit word offsets)
#define SM_SBITS   0           // 512
#define SM_SCOUNT  512         // 16
#define SM_TASK    528         // 1 (+15 pad)
#define SM_SLIST   544         // 16*1024
#define SM_MEM     16928       // 2048 floats
#define SM_WORDS   18976
#define SMEM_SCAN  (SM_WORDS * 4)

// ---------------------------------------------------------------------------
// Row-group barrier: 8 blocks sharing rg. Self-restoring across replays.
// ---------------------------------------------------------------------------
__device__ __forceinline__ void group_barrier(int rg) {
    __threadfence();
    __syncthreads();
    if (threadIdx.x == 0) {
        unsigned gen = *(volatile unsigned*)&g_grpGen[rg];
        unsigned arr = atomicAdd(&g_grpCnt[rg], 1u);
        if (arr == GROUP_SZ - 1) {
            g_grpCnt[rg] = 0;
            __threadfence();
            *(volatile unsigned*)&g_grpGen[rg] = gen + 1u;
        } else {
            while (*(volatile unsigned*)&g_grpGen[rg] == gen) { }
        }
    }
    __syncthreads();
}

// Packed f32x2 add: each half rounds exactly like scalar add.rn.f32
// (== the reference's fma(1.0, v, acc) chain step).
__device__ __forceinline__ ull padd(ull a, ull b) {
    ull r;
    asm("add.rn.f32x2 %0, %1, %2;" : "=l"(r) : "l"(a), "l"(b));
    return r;
}

// spread 32 bits: bit i -> bit 2i
__device__ __forceinline__ ull spread2(unsigned v) {
    ull x = v;
    x = (x | (x << 16)) & 0x0000FFFF0000FFFFull;
    x = (x | (x << 8))  & 0x00FF00FF00FF00FFull;
    x = (x | (x << 4))  & 0x0F0F0F0F0F0F0F0Full;
    x = (x | (x << 2))  & 0x3333333333333333ull;
    x = (x | (x << 1))  & 0x5555555555555555ull;
    return x;
}

// ---------------------------------------------------------------------------
// Encode: z = relu(x @ W_enc + b_enc). FLAT ascending-k single-accumulator
// FFMA chain per element; bias-add and relu separately rounded. (Frozen.)
// Register-prefetch double buffering. Block (0,0) also zeroes g_bits[0]
// and the group-barrier state.
// ---------------------------------------------------------------------------
__global__ void __launch_bounds__(256, 2) encode_kernel(
    const float* __restrict__ X, const float* __restrict__ W,
    const float* __restrict__ bias)
{
    __shared__ float As[16][128];
    __shared__ float Bs[16][128];

    const int bm = blockIdx.y;
    const int bn = blockIdx.x;
    const int tid = threadIdx.x;

    if (bm == 0 && bn == 0) {
        unsigned* bz = &g_bits[0][0][0];
#pragma unroll
        for (int l = 0; l < (BATCH * (HID / 32)) / 256; ++l)
            bz[tid + l * 256] = 0u;
        if (tid < 16) { g_grpCnt[tid] = 0u; g_grpGen[tid] = 0u; }
    }

    const int trow = (tid >> 4) * 8;
    const int tcol = (tid & 15) * 8;

    const float* A0 = X + (size_t)bm * 128 * DIM;
    const float* B0 = W + bn * 128;

    const int ar0 = tid >> 2,          ak0 = (tid & 3) * 4;
    const int ar1 = (tid + 256) >> 2,  ak1 = ((tid + 256) & 3) * 4;
    const int br0 = tid >> 5,          bc0 = (tid & 31) * 4;
    const int br1 = (tid + 256) >> 5,  bc1 = ((tid + 256) & 31) * 4;

    float acc[8][8];
#pragma unroll
    for (int i = 0; i < 8; ++i)
#pragma unroll
        for (int j = 0; j < 8; ++j) acc[i][j] = 0.f;

    float4 pa0 = *(const float4*)(A0 + (size_t)ar0 * DIM + ak0);
    float4 pa1 = *(const float4*)(A0 + (size_t)ar1 * DIM + ak1);
    float4 pb0 = *(const float4*)(B0 + (size_t)br0 * HID + bc0);
    float4 pb1 = *(const float4*)(B0 + (size_t)br1 * HID + bc1);

    for (int kt = 0; kt < DIM; kt += 16) {
        As[ak0 + 0][ar0] = pa0.x; As[ak0 + 1][ar0] = pa0.y;
        As[ak0 + 2][ar0] = pa0.z; As[ak0 + 3][ar0] = pa0.w;
        As[ak1 + 0][ar1] = pa1.x; As[ak1 + 1][ar1] = pa1.y;
        As[ak1 + 2][ar1] = pa1.z; As[ak1 + 3][ar1] = pa1.w;
        *(float4*)&Bs[br0][bc0] = pb0;
        *(float4*)&Bs[br1][bc1] = pb1;
        __syncthreads();

        if (kt + 16 < DIM) {
            pa0 = *(const float4*)(A0 + (size_t)ar0 * DIM + (kt + 16) + ak0);
            pa1 = *(const float4*)(A0 + (size_t)ar1 * DIM + (kt + 16) + ak1);
            pb0 = *(const float4*)(B0 + (size_t)(kt + 16 + br0) * HID + bc0);
            pb1 = *(const float4*)(B0 + (size_t)(kt + 16 + br1) * HID + bc1);
        }

#pragma unroll
        for (int kk = 0; kk < 16; ++kk) {
            float ra[8], rb[8];
#pragma unroll
            for (int i = 0; i < 8; ++i) ra[i] = As[kk][trow + i];
#pragma unroll
            for (int j = 0; j < 8; ++j) rb[j] = Bs[kk][tcol + j];
#pragma unroll
            for (int i = 0; i < 8; ++i)
#pragma unroll
                for (int j = 0; j < 8; ++j)
                    acc[i][j] = __fmaf_rn(ra[i], rb[j], acc[i][j]);
        }
        __syncthreads();
    }

    const int m0 = bm * 128 + trow;
    const int n0 = bn * 128 + tcol;
    float bb[8];
#pragma unroll
    for (int j = 0; j < 8; ++j) bb[j] = bias[n0 + j];
#pragma unroll
    for (int i = 0; i < 8; ++i) {
        int m = m0 + i;
        int b = m >> 9;
        int s = m & 511;
        float* dst = g_z + ((size_t)s * BATCH + b) * HID + n0;
        float r[8];
#pragma unroll
        for (int j = 0; j < 8; ++j)
            r[j] = fmaxf(__fadd_rn(acc[i][j], bb[j]), 0.f);
        ((float4*)dst)[0] = make_float4(r[0], r[1], r[2], r[3]);
        ((float4*)dst)[1] = make_float4(r[4], r[5], r[6], r[7]);
    }
}

// ---------------------------------------------------------------------------
// Scan: persistent, 128 blocks x 512 threads. Block = 16 rows x 128 cols.
// 32 dynamic tasks = (row, 64-col half); lane covers 2 adjacent cols.
//
// Bit layout: within row, word = 4*cg + 2*h + r (h = col-half, r = col&1),
// bit l  <->  col = 128*cg + 64*h + 2*l + r.
// Chains: per (row,col) full ascending-j single-accumulator FADD (frozen).
// Membrane: fma(0.95, mem, z) then +G, +bv, -rst separately rounded (frozen).
// Row-groups (16 rows) are independent -> 8-block group barriers only.
// ---------------------------------------------------------------------------
__global__ void __launch_bounds__(512, 1) scan_kernel(
    const float* __restrict__ V,      const float* __restrict__ b_v,
    const float* __restrict__ W_pol,  const float* __restrict__ b_pol,
    const float* __restrict__ W_size, const float* __restrict__ b_size,
    const float* __restrict__ W_val,  const float* __restrict__ b_val,
    float* __restrict__ out)
{
    extern __shared__ unsigned smx[];
    unsigned* sbits   = smx + SM_SBITS;
    unsigned* scount  = smx + SM_SCOUNT;
    unsigned* taskctr = smx + SM_TASK;
    unsigned* slist   = smx + SM_SLIST;
    float*    smem_mem = (float*)(smx + SM_MEM);   // [row][col] 16x128

    const int tid  = threadIdx.x;
    const int bid  = blockIdx.x;
    const int rg   = bid >> 3;
    const int cg   = bid & 7;
    const int r0   = rg * 16;
    const int c0   = cg * 128;
    const int lane = tid & 31;

    // zero mem state
    for (int i = tid; i < 16 * 128; i += 512) smem_mem[i] = 0.f;
    group_barrier(rg);          // also ensures encode's g_bits[0] zeroing done
                                // (kernel-launch order guarantees data; this
                                // aligns the group before step 0)

    for (int t = 0; t < SEQ; ++t) {
        // stage this block's 16 rows of spike bits (512 words)
        const unsigned* curbits = &g_bits[t % 3][0][0] + (size_t)r0 * 32;
        sbits[tid] = __ldcg(curbits + tid);
        if (tid == 0) *taskctr = 0u;
        __syncthreads();

        // build per-row ascending firing lists (threads 0..255):
        // thread (brow = tid>>4, g = tid&15); group g = j in [64g, 64g+64)
        if (tid < 256) {
            const int brow = tid >> 4;
            const int g    = tid & 15;
            // words for this group: idx = 4*(g>>1) + 2*(g&1) + {0,1}
            const unsigned* wp = sbits + brow * 32 + 4 * (g >> 1) + 2 * (g & 1);
            ull M = spread2(wp[0]) | (spread2(wp[1]) << 1);
            unsigned cnt = __popcll(M);
            unsigned inc = cnt;
#pragma unroll
            for (int d2 = 1; d2 < 16; d2 <<= 1) {
                unsigned tt = __shfl_up_sync(0xffffffffu, inc, d2, 16);
                if ((tid & 15) >= d2) inc += tt;
            }
            unsigned wpos = brow * 1024 + (inc - cnt);
            int jb = g * 64;
            while (M) {
                int pos = __ffsll(M) - 1;
                M &= M - 1;
                slist[wpos++] = (unsigned)((jb + pos) << 12);  // byte offs j*4096
            }
            if ((tid & 15) == 15) scount[brow] = inc;
        }
        __syncthreads();

        // dynamic task consumption: 32 tasks = (row, half), 16 warps
        unsigned* dstb = &g_bits[(t + 1) % 3][0][0];
        for (;;) {
            unsigned task = 0;
            if (lane == 0) task = atomicAdd(taskctr, 1u);
            task = __shfl_sync(0xffffffffu, task, 0);
            if (task >= 32) break;
            const int row = task >> 1;
            const int h   = task & 1;
            const int c   = c0 + 64 * h + 2 * lane;   // 2 adjacent cols
            const char* Vb = (const char*)V + (size_t)c * 4;

            float2 zz = *(const float2*)(g_z +
                          ((size_t)t * BATCH + r0 + row) * HID + c);
            float2 bv = *(const float2*)(b_v + c);

            const int n = scount[row];
            const unsigned* lp = slist + row * 1024;
            ull a = 0ull;
            int i = 0;
            for (; i + 8 <= n; i += 8) {
                uint4 oa = *(const uint4*)(lp + i);
                uint4 ob = *(const uint4*)(lp + i + 4);
                ull v0 = *(const ull*)(Vb + oa.x);
                ull v1 = *(const ull*)(Vb + oa.y);
                ull v2 = *(const ull*)(Vb + oa.z);
                ull v3 = *(const ull*)(Vb + oa.w);
                ull v4 = *(const ull*)(Vb + ob.x);
                ull v5 = *(const ull*)(Vb + ob.y);
                ull v6 = *(const ull*)(Vb + ob.z);
                ull v7 = *(const ull*)(Vb + ob.w);
                a = padd(a, v0); a = padd(a, v1);
                a = padd(a, v2); a = padd(a, v3);
                a = padd(a, v4); a = padd(a, v5);
                a = padd(a, v6); a = padd(a, v7);
            }
            for (; i < n; ++i)
                a = padd(a, *(const ull*)(Vb + lp[i]));
            float2 gg = *(float2*)&a;

            // membrane (frozen semantics); reset = (incoming mem > 1)
            float* mp = smem_mem + row * 128 + 64 * h + 2 * lane;
            float m0v = mp[0], m1v = mp[1];
            float rst0 = (m0v > 1.0f) ? 1.0f : 0.0f;
            float rst1 = (m1v > 1.0f) ? 1.0f : 0.0f;
            m0v = __fsub_rn(__fadd_rn(__fadd_rn(
                      __fmaf_rn(0.95f, m0v, zz.x), gg.x), bv.x), rst0);
            m1v = __fsub_rn(__fadd_rn(__fadd_rn(
                      __fmaf_rn(0.95f, m1v, zz.y), gg.y), bv.y), rst1);
            mp[0] = m0v; mp[1] = m1v;

            unsigned br0b = __ballot_sync(0xffffffffu, m0v > 1.0f);
            unsigned br1b = __ballot_sync(0xffffffffu, m1v > 1.0f);
            if (lane == 0) {
                // words (row, 4cg + 2h + {0,1}) -> one STG.64
                ull wv = (ull)br0b | ((ull)br1b << 32);
                *(ull*)(dstb + (r0 + row) * 32 + 4 * cg + 2 * h) = wv;
            }
        }

        group_barrier(rg);
    }

    // Heads: tail spikes in g_bits[512 % 3 == 2]. Rows 2*bid, 2*bid+1 are in
    // this block's row-group -> visible after the final group barrier.
    // Layout: word = 4*(j>>7) + 2*((j>>6)&1) + (j&1), bit = (j>>1)&31.
    const unsigned* tail = &g_bits[2][0][0];
    if (tid < 22) {
        int r = bid * 2 + tid / 11;
        int o = tid % 11;
        const float* Wp; int stride; float bo_;
        if (o < 6)       { Wp = W_pol  + o;       stride = NA; bo_ = b_pol[o]; }
        else if (o < 10) { Wp = W_size + (o - 6); stride = NS; bo_ = b_size[o - 6]; }
        else             { Wp = W_val;            stride = 1;  bo_ = b_val[0]; }
        float s = 0.f;
        for (int j = 0; j < HID; ++j) {
            unsigned word = __ldcg(tail + r * 32 +
                                   (4 * (j >> 7) + 2 * ((j >> 6) & 1) + (j & 1)));
            if ((word >> ((j >> 1) & 31)) & 1u)
                s = __fadd_rn(s, Wp[(size_t)j * stride]);
        }
        float val = __fadd_rn(s, bo_);
        if (o < 6)       out[r * NA + o] = val;
        else if (o < 10) out[BATCH * NA + r * NS + (o - 6)] = val;
        else             out[BATCH * NA + BATCH * NS + r] = val;
    }
}

// ---------------------------------------------------------------------------
extern "C" void kernel_launch(void* const* d_in, const int* in_sizes, int n_in,
                              void* d_out, int out_size) {
    const float* x      = (const float*)d_in[0];
    const float* W_enc  = (const float*)d_in[1];
    const float* b_enc  = (const float*)d_in[2];
    const float* V      = (const float*)d_in[3];
    const float* b_v    = (const float*)d_in[4];
    const float* W_pol  = (const float*)d_in[5];
    const float* b_pol  = (const float*)d_in[6];
    const float* W_size = (const float*)d_in[7];
    const float* b_size = (const float*)d_in[8];
    const float* W_val  = (const float*)d_in[9];
    const float* b_val  = (const float*)d_in[10];
    float* out = (float*)d_out;

    cudaFuncSetAttribute(scan_kernel,
        cudaFuncAttributeMaxDynamicSharedMemorySize, SMEM_SCAN);

    dim3 eg(HID / 128, (BATCH * SEQ) / 128);
    encode_kernel<<<eg, 256>>>(x, W_enc, b_enc);

    scan_kernel<<<GRID_SCAN, 512, SMEM_SCAN>>>(V, b_v, W_pol, b_pol,
                                               W_size, b_size, W_val, b_val, out);
}

// round 16
// speedup vs baseline: 1.9512x; 1.1115x over previous
#include <cuda_runtime.h>
#include <cstdint>

#define BATCH 256
#define SEQ   512
#define DIM   512
#define HID   1024
#define NA    6
#define NS    4

typedef unsigned long long ull;

// ---------------------------------------------------------------------------
// Device scratch (static; no cudaMalloc allowed)
// ---------------------------------------------------------------------------
__device__ float    g_z[(size_t)SEQ * BATCH * HID];       // z [S][B][H]
__device__ __align__(16) unsigned g_bits[3][BATCH][HID / 32]; // spike bitmasks
__device__ unsigned g_grpCnt[16];                          // per-rowgroup barrier
__device__ unsigned g_grpGen[16];

#define GRID_SCAN 128
#define GROUP_SZ  8            // blocks per row-group barrier
// dynamic smem: sbits[512] + scount[16]+pad[16] + slist[16][1024]
#define SMEM_SCAN ((512 + 32 + 16 * 1024) * 4)

// ---------------------------------------------------------------------------
// Row-group barrier: 8 blocks sharing rg (batch rows are independent across
// groups; only blocks with the same 16 rows exchange spike bits).
// Self-restoring across graph replays.
// ---------------------------------------------------------------------------
__device__ __forceinline__ void group_barrier(int rg) {
    __threadfence();
    __syncthreads();
    if (threadIdx.x == 0) {
        unsigned gen = *(volatile unsigned*)&g_grpGen[rg];
        unsigned arr = atomicAdd(&g_grpCnt[rg], 1u);
        if (arr == GROUP_SZ - 1) {
            g_grpCnt[rg] = 0;
            __threadfence();
            *(volatile unsigned*)&g_grpGen[rg] = gen + 1u;
        } else {
            while (*(volatile unsigned*)&g_grpGen[rg] == gen) { }
        }
    }
    __syncthreads();
}

// Packed f32x2 add: each half rounds exactly like scalar add.rn.f32
// (== the reference's fma(1.0, v, acc) chain step).
__device__ __forceinline__ ull padd(ull a, ull b) {
    ull r;
    asm("add.rn.f32x2 %0, %1, %2;" : "=l"(r) : "l"(a), "l"(b));
    return r;
}

// spread 16 bits: bit i -> bit 4i of a 64-bit word
__device__ __forceinline__ ull spread4(unsigned h) {
    ull x = h;
    x = (x | (x << 24)) & 0x000000FF000000FFull;
    x = (x | (x << 12)) & 0x000F000F000F000Full;
    x = (x | (x << 6))  & 0x0303030303030303ull;
    x = (x | (x << 3))  & 0x1111111111111111ull;
    return x;
}

// ---------------------------------------------------------------------------
// Encode: z = relu(x @ W_enc + b_enc). FLAT ascending-k single-accumulator
// FFMA chain per element; bias-add and relu separately rounded. (Frozen.)
// Register-prefetch double buffering. Block (0,0) also zeroes g_bits[0]
// and the group-barrier state.
// ---------------------------------------------------------------------------
__global__ void __launch_bounds__(256, 2) encode_kernel(
    const float* __restrict__ X, const float* __restrict__ W,
    const float* __restrict__ bias)
{
    __shared__ float As[16][128];
    __shared__ float Bs[16][128];

    const int bm = blockIdx.y;
    const int bn = blockIdx.x;
    const int tid = threadIdx.x;

    if (bm == 0 && bn == 0) {
        unsigned* bz = &g_bits[0][0][0];
#pragma unroll
        for (int l = 0; l < (BATCH * (HID / 32)) / 256; ++l)
            bz[tid + l * 256] = 0u;
        if (tid < 16) { g_grpCnt[tid] = 0u; g_grpGen[tid] = 0u; }
    }

    const int trow = (tid >> 4) * 8;
    const int tcol = (tid & 15) * 8;

    const float* A0 = X + (size_t)bm * 128 * DIM;
    const float* B0 = W + bn * 128;

    const int ar0 = tid >> 2,          ak0 = (tid & 3) * 4;
    const int ar1 = (tid + 256) >> 2,  ak1 = ((tid + 256) & 3) * 4;
    const int br0 = tid >> 5,          bc0 = (tid & 31) * 4;
    const int br1 = (tid + 256) >> 5,  bc1 = ((tid + 256) & 31) * 4;

    float acc[8][8];
#pragma unroll
    for (int i = 0; i < 8; ++i)
#pragma unroll
        for (int j = 0; j < 8; ++j) acc[i][j] = 0.f;

    float4 pa0 = *(const float4*)(A0 + (size_t)ar0 * DIM + ak0);
    float4 pa1 = *(const float4*)(A0 + (size_t)ar1 * DIM + ak1);
    float4 pb0 = *(const float4*)(B0 + (size_t)br0 * HID + bc0);
    float4 pb1 = *(const float4*)(B0 + (size_t)br1 * HID + bc1);

    for (int kt = 0; kt < DIM; kt += 16) {
        As[ak0 + 0][ar0] = pa0.x; As[ak0 + 1][ar0] = pa0.y;
        As[ak0 + 2][ar0] = pa0.z; As[ak0 + 3][ar0] = pa0.w;
        As[ak1 + 0][ar1] = pa1.x; As[ak1 + 1][ar1] = pa1.y;
        As[ak1 + 2][ar1] = pa1.z; As[ak1 + 3][ar1] = pa1.w;
        *(float4*)&Bs[br0][bc0] = pb0;
        *(float4*)&Bs[br1][bc1] = pb1;
        __syncthreads();

        if (kt + 16 < DIM) {
            pa0 = *(const float4*)(A0 + (size_t)ar0 * DIM + (kt + 16) + ak0);
            pa1 = *(const float4*)(A0 + (size_t)ar1 * DIM + (kt + 16) + ak1);
            pb0 = *(const float4*)(B0 + (size_t)(kt + 16 + br0) * HID + bc0);
            pb1 = *(const float4*)(B0 + (size_t)(kt + 16 + br1) * HID + bc1);
        }

#pragma unroll
        for (int kk = 0; kk < 16; ++kk) {
            float ra[8], rb[8];
#pragma unroll
            for (int i = 0; i < 8; ++i) ra[i] = As[kk][trow + i];
#pragma unroll
            for (int j = 0; j < 8; ++j) rb[j] = Bs[kk][tcol + j];
#pragma unroll
            for (int i = 0; i < 8; ++i)
#pragma unroll
                for (int j = 0; j < 8; ++j)
                    acc[i][j] = __fmaf_rn(ra[i], rb[j], acc[i][j]);
        }
        __syncthreads();
    }

    const int m0 = bm * 128 + trow;
    const int n0 = bn * 128 + tcol;
    float bb[8];
#pragma unroll
    for (int j = 0; j < 8; ++j) bb[j] = bias[n0 + j];
#pragma unroll
    for (int i = 0; i < 8; ++i) {
        int m = m0 + i;
        int b = m >> 9;
        int s = m & 511;
        float* dst = g_z + ((size_t)s * BATCH + b) * HID + n0;
        float r[8];
#pragma unroll
        for (int j = 0; j < 8; ++j)
            r[j] = fmaxf(__fadd_rn(acc[i][j], bb[j]), 0.f);
        ((float4*)dst)[0] = make_float4(r[0], r[1], r[2], r[3]);
        ((float4*)dst)[1] = make_float4(r[4], r[5], r[6], r[7]);
    }
}

// ---------------------------------------------------------------------------
// Scan: persistent, 128 blocks x 512 threads (16 warps). Block = 16 rows x
// 128 cols. Warp u owns row u; lane owns 4 adjacent cols (c = c0 + 4*lane).
//
// Bit layout: word (row, 4*cg + r), bit l  <->  col/j = 128*cg + 4*l + r.
// Per step: masks -> per-row ascending firing-index lists (byte offsets
// j*4096) in smem, then a pure FADD2 stream over LDG.128 V rows, unroll x8.
// Exactness: visits = exactly the firing j's ascending == the reference's
// flat ascending-k chain. Membrane: fma(0.95, mem, z) then +G, +bv, -rst
// separately rounded. (Frozen semantics.)
// Row-group barriers only (8 blocks) — groups are independent.
// ---------------------------------------------------------------------------
__global__ void __launch_bounds__(512, 1) scan_kernel(
    const float* __restrict__ V,      const float* __restrict__ b_v,
    const float* __restrict__ W_pol,  const float* __restrict__ b_pol,
    const float* __restrict__ W_size, const float* __restrict__ b_size,
    const float* __restrict__ W_val,  const float* __restrict__ b_val,
    float* __restrict__ out)
{
    extern __shared__ unsigned smx[];
    unsigned* sbits  = smx;            // [16][32]
    unsigned* scount = smx + 512;      // [16] (+16 pad)
    unsigned* slist  = smx + 544;      // [16][1024]

    const int tid  = threadIdx.x;
    const int bid  = blockIdx.x;
    const int rg   = bid >> 3;
    const int cg   = bid & 7;
    const int r0   = rg * 16;
    const int c0   = cg * 128;
    const int u    = tid >> 5;          // warp id 0..15 -> row u
    const int lane = tid & 31;
    const int c    = c0 + 4 * lane;     // first of 4 adjacent cols

    const char* Vb = (const char*)V + (size_t)c * 4;

    float4 mem4 = make_float4(0.f, 0.f, 0.f, 0.f);
    unsigned ps = 0u;                   // 4 spike bits (cols c..c+3)

    const float4 bv4 = *(const float4*)(b_v + c);

    for (int t = 0; t < SEQ; ++t) {
        // z prefetch (independent -> latency hidden under list build)
        float4 zz = *(const float4*)(g_z +
                      ((size_t)t * BATCH + r0 + u) * HID + c);

        // stage this block's 16 rows of spike bits (512 words, 1 per thread)
        const unsigned* curbits = &g_bits[t % 3][0][0] + (size_t)r0 * 32;
        sbits[tid] = __ldcg(curbits + tid);
        __syncthreads();

        // build per-row ascending firing lists (threads 0..255)
        if (tid < 256) {
            const int brow = tid >> 4;
            const int g    = tid & 15;
            const unsigned* wp = sbits + brow * 32 + 4 * (g >> 1);
            ull M = 0;
#pragma unroll
            for (int r = 0; r < 4; ++r) {
                unsigned w = wp[r];
                unsigned h = (g & 1) ? (w >> 16) : (w & 0xFFFFu);
                M |= spread4(h) << r;
            }
            unsigned cnt = __popcll(M);
            unsigned inc = cnt;
#pragma unroll
            for (int d2 = 1; d2 < 16; d2 <<= 1) {
                unsigned tt = __shfl_up_sync(0xffffffffu, inc, d2, 16);
                if ((tid & 15) >= d2) inc += tt;
            }
            unsigned wpos = brow * 1024 + (inc - cnt);
            int jb = g * 64;
            while (M) {
                int pos = __ffsll(M) - 1;
                M &= M - 1;
                slist[wpos++] = (unsigned)((jb + pos) << 12);  // byte offs j*4096
            }
            if ((tid & 15) == 15) scount[brow] = inc;
        }
        __syncthreads();

        // consume: pure FADD2 stream over this row's firing list, unroll x8
        const int n = scount[u];
        const unsigned* lp = slist + u * 1024;
        ull a0 = 0ull, a1 = 0ull;
        int i = 0;
        for (; i + 8 <= n; i += 8) {
            uint4 oa = *(const uint4*)(lp + i);
            uint4 ob = *(const uint4*)(lp + i + 4);
            ulonglong2 v0 = *(const ulonglong2*)(Vb + oa.x);
            ulonglong2 v1 = *(const ulonglong2*)(Vb + oa.y);
            ulonglong2 v2 = *(const ulonglong2*)(Vb + oa.z);
            ulonglong2 v3 = *(const ulonglong2*)(Vb + oa.w);
            ulonglong2 v4 = *(const ulonglong2*)(Vb + ob.x);
            ulonglong2 v5 = *(const ulonglong2*)(Vb + ob.y);
            ulonglong2 v6 = *(const ulonglong2*)(Vb + ob.z);
            ulonglong2 v7 = *(const ulonglong2*)(Vb + ob.w);
            a0 = padd(a0, v0.x); a1 = padd(a1, v0.y);
            a0 = padd(a0, v1.x); a1 = padd(a1, v1.y);
            a0 = padd(a0, v2.x); a1 = padd(a1, v2.y);
            a0 = padd(a0, v3.x); a1 = padd(a1, v3.y);
            a0 = padd(a0, v4.x); a1 = padd(a1, v4.y);
            a0 = padd(a0, v5.x); a1 = padd(a1, v5.y);
            a0 = padd(a0, v6.x); a1 = padd(a1, v6.y);
            a0 = padd(a0, v7.x); a1 = padd(a1, v7.y);
        }
        for (; i < n; ++i) {
            ulonglong2 v = *(const ulonglong2*)(Vb + lp[i]);
            a0 = padd(a0, v.x); a1 = padd(a1, v.y);
        }
        float2 g01 = *(float2*)&a0;
        float2 g23 = *(float2*)&a1;

        // membrane (frozen semantics)
        float gg[4] = {g01.x, g01.y, g23.x, g23.y};
        float zv[4] = {zz.x, zz.y, zz.z, zz.w};
        float mv[4] = {mem4.x, mem4.y, mem4.z, mem4.w};
        float bb[4] = {bv4.x, bv4.y, bv4.z, bv4.w};
        float m[4];
        unsigned np = 0;
#pragma unroll
        for (int k = 0; k < 4; ++k) {
            float rst = ((ps >> k) & 1u) ? 1.0f : 0.0f;
            m[k] = __fsub_rn(__fadd_rn(__fadd_rn(
                       __fmaf_rn(0.95f, mv[k], zv[k]), gg[k]), bb[k]), rst);
            np |= (m[k] > 1.0f ? 1u : 0u) << k;
        }
        mem4 = make_float4(m[0], m[1], m[2], m[3]);
        ps = np;

        // publish: 4 ballots, one STG.128 from lane 0
        unsigned b0 = __ballot_sync(0xffffffffu, (np >> 0) & 1u);
        unsigned b1 = __ballot_sync(0xffffffffu, (np >> 1) & 1u);
        unsigned b2 = __ballot_sync(0xffffffffu, (np >> 2) & 1u);
        unsigned b3 = __ballot_sync(0xffffffffu, (np >> 3) & 1u);
        if (lane == 0) {
            unsigned* dstb = &g_bits[(t + 1) % 3][0][0];
            *(uint4*)(dstb + (r0 + u) * 32 + 4 * cg) = make_uint4(b0, b1, b2, b3);
        }

        group_barrier(rg);
    }

    // Heads: tail spikes in g_bits[512 % 3 == 2]; rows 2*bid, 2*bid+1 are in
    // this block's row-group -> visible after its final group barrier.
    // Layout: word = 4*(j>>7) + (j&3), bit = (j>>2)&31.
    const unsigned* tail = &g_bits[2][0][0];
    if (tid < 22) {
        int r = bid * 2 + tid / 11;
        int o = tid % 11;
        const float* Wp; int stride; float bo_;
        if (o < 6)       { Wp = W_pol  + o;       stride = NA; bo_ = b_pol[o]; }
        else if (o < 10) { Wp = W_size + (o - 6); stride = NS; bo_ = b_size[o - 6]; }
        else             { Wp = W_val;            stride = 1;  bo_ = b_val[0]; }
        float s = 0.f;
        for (int j = 0; j < HID; ++j) {
            unsigned word = __ldcg(tail + r * 32 + (4 * (j >> 7) + (j & 3)));
            if ((word >> ((j >> 2) & 31)) & 1u)
                s = __fadd_rn(s, Wp[(size_t)j * stride]);
        }
        float val = __fadd_rn(s, bo_);
        if (o < 6)       out[r * NA + o] = val;
        else if (o < 10) out[BATCH * NA + r * NS + (o - 6)] = val;
        else             out[BATCH * NA + BATCH * NS + r] = val;
    }
}

// ---------------------------------------------------------------------------
extern "C" void kernel_launch(void* const* d_in, const int* in_sizes, int n_in,
                              void* d_out, int out_size) {
    const float* x      = (const float*)d_in[0];
    const float* W_enc  = (const float*)d_in[1];
    const float* b_enc  = (const float*)d_in[2];
    const float* V      = (const float*)d_in[3];
    const float* b_v    = (const float*)d_in[4];
    const float* W_pol  = (const float*)d_in[5];
    const float* b_pol  = (const float*)d_in[6];
    const float* W_size = (const float*)d_in[7];
    const float* b_size = (const float*)d_in[8];
    const float* W_val  = (const float*)d_in[9];
    const float* b_val  = (const float*)d_in[10];
    float* out = (float*)d_out;

    cudaFuncSetAttribute(scan_kernel,
        cudaFuncAttributeMaxDynamicSharedMemorySize, SMEM_SCAN);

    dim3 eg(HID / 128, (BATCH * SEQ) / 128);
    encode_kernel<<<eg, 256>>>(x, W_enc, b_enc);

    scan_kernel<<<GRID_SCAN, 512, SMEM_SCAN>>>(V, b_v, W_pol, b_pol,
                                               W_size, b_size, W_val, b_val, out);
}